// round 9
// baseline (speedup 1.0000x reference)
#include <cuda_runtime.h>
#include <cuda_bf16.h>
#include <cstdint>
#include <cstddef>

// Problem dims
#define TT 2048
#define NB 32
#define UU 256
#define OUT_MAIN ((size_t)NB * TT * 512)
#define OUT_FULL (OUT_MAIN + 4 * (size_t)NB * UU)
#define HSEQ_SLOTS (TT + 1)
#define CANARY 0x7fc0deadu

// ---------------- static device scratch ----------------
__device__ float g_xz[(size_t)TT * NB * 2048];   // [t*32+b][2048] gate preacts
__device__ float g_X1[(size_t)TT * NB * 512];    // layer0 output [t][b][512]
__device__ float g_X2[(size_t)TT * NB * 512];    // layer1 output
__device__ float g_Ure[3][2][UU * 1024];         // [layer][dir][k][u*4+g]
__device__ float g_Wcat[2][512 * 2048];          // [l][k][d*1024 + u*4+g]
__device__ float g_bcat[2][2048];
__device__ float g_W0re[2][1024];
__device__ float g_b0re[2][1024];
__device__ float g_hseq[(size_t)HSEQ_SLOTS * 2 * UU * NB];  // [slot][dir][u*32+b]
__device__ float g_stateH[2][UU * NB];
__device__ float g_stateC[2][UU * NB];

// ---------------- packed f32x2 helpers ----------------
__device__ __forceinline__ void fma2(unsigned long long& d, unsigned long long a,
                                     unsigned long long b) {
    asm("fma.rn.f32x2 %0, %1, %2, %0;" : "+l"(d) : "l"(a), "l"(b));
}
__device__ __forceinline__ void add2(unsigned long long& d, unsigned long long a) {
    asm("add.rn.f32x2 %0, %0, %1;" : "+l"(d) : "l"(a));
}
__device__ __forceinline__ unsigned long long pack2(float x) {
    unsigned long long r;
    asm("mov.b64 %0, {%1, %1};" : "=l"(r) : "f"(x));
    return r;
}
__device__ __forceinline__ unsigned long long pack2b(float x, float y) {
    unsigned long long r;
    asm("mov.b64 %0, {%1, %2};" : "=l"(r) : "f"(x), "f"(y));
    return r;
}
__device__ __forceinline__ float2 unpack2(unsigned long long v) {
    float2 f;
    asm("mov.b64 {%0, %1}, %2;" : "=f"(f.x), "=f"(f.y) : "l"(v));
    return f;
}
__device__ __forceinline__ unsigned ld_relax(const float* p) {
    unsigned v;
    asm volatile("ld.relaxed.gpu.global.b32 %0, [%1];" : "=r"(v) : "l"(p) : "memory");
    return v;
}
__device__ __forceinline__ void st_relax(float* p, float v) {
    asm volatile("st.relaxed.gpu.global.b32 [%0], %1;" :: "l"(p), "f"(v) : "memory");
}

// ---------------- fast-math-immune activations ----------------
__device__ __forceinline__ float exp_p(float x) {
    float t = fminf(fmaxf(x, -87.0f), 87.0f);
    float n = rintf(t * 1.4426950408889634f);
    float f = fmaf(n, -0.693145751953125f, t);
    f = fmaf(n, -1.4286067653e-06f, f);
    float p = 1.9841270e-04f;
    p = fmaf(p, f, 1.3888889e-03f);
    p = fmaf(p, f, 8.3333333e-03f);
    p = fmaf(p, f, 4.1666668e-02f);
    p = fmaf(p, f, 1.6666667e-01f);
    p = fmaf(p, f, 0.5f);
    p = fmaf(p, f, 1.0f);
    p = fmaf(p, f, 1.0f);
    int ni = (int)n;
    float sc = __int_as_float((ni + 127) << 23);
    return p * sc;
}
__device__ __forceinline__ float rcp_nr(float d) {
    float r;
    asm("rcp.approx.f32 %0, %1;" : "=f"(r) : "f"(d));
    r = fmaf(r, fmaf(-d, r, 1.0f), r);
    return r;
}
__device__ __forceinline__ float sig_p(float x) {
    return rcp_nr(1.0f + exp_p(-x));
}
__device__ __forceinline__ float tanh_p(float x) {
    float a = fabsf(x);
    float e = exp_p(-2.0f * a);
    float r = (1.0f - e) * rcp_nr(1.0f + e);
    return copysignf(r, x);
}

// ---------------- weight rearrangement ----------------
__global__ void prep_kernel(const float* __restrict__ W0f, const float* __restrict__ U0f,
                            const float* __restrict__ b0f, const float* __restrict__ W0b,
                            const float* __restrict__ U0b, const float* __restrict__ b0b,
                            const float* __restrict__ Wf, const float* __restrict__ Uf,
                            const float* __restrict__ bf, const float* __restrict__ Wb,
                            const float* __restrict__ Ub, const float* __restrict__ bb) {
    int idx0 = blockIdx.x * blockDim.x + threadIdx.x;
    int stride = gridDim.x * blockDim.x;
    for (int i = idx0; i < 3 * 2 * 256 * 1024; i += stride) {
        int j = i & 1023;
        int k = (i >> 10) & 255;
        int d = (i >> 18) & 1;
        int l = i >> 19;
        int u = j >> 2, g = j & 3;
        const float* Us = (l == 0) ? (d ? U0b : U0f)
                                   : (d ? Ub + (size_t)(l - 1) * 256 * 1024
                                        : Uf + (size_t)(l - 1) * 256 * 1024);
        g_Ure[l][d][k * 1024 + j] = Us[k * 1024 + g * 256 + u];
    }
    for (int i = idx0; i < 2 * 512 * 2048; i += stride) {
        int j2 = i & 2047;
        int k = (i >> 11) & 511;
        int l = i >> 20;
        int d = j2 >> 10;
        int j = j2 & 1023;
        int u = j >> 2, g = j & 3;
        const float* Ws = d ? Wb : Wf;
        g_Wcat[l][k * 2048 + j2] = Ws[(size_t)l * 512 * 1024 + k * 1024 + g * 256 + u];
    }
    for (int i = idx0; i < 2 * 2048; i += stride) {
        int j2 = i & 2047;
        int l = i >> 11;
        int d = j2 >> 10;
        int j = j2 & 1023;
        int u = j >> 2, g = j & 3;
        const float* bs = d ? bb : bf;
        g_bcat[l][j2] = bs[l * 1024 + g * 256 + u];
    }
    for (int i = idx0; i < 2 * 1024; i += stride) {
        int j = i & 1023;
        int d = i >> 10;
        int u = j >> 2, g = j & 3;
        g_W0re[d][j] = (d ? W0b : W0f)[g * 256 + u];
        g_b0re[d][j] = (d ? b0b : b0f)[g * 256 + u];
    }
}

// ---------------- per-layer init: slot0 = h0, slots 1..TT = canary ----------------
__global__ void pre_recur_kernel(int zero_init) {
    size_t idx = (size_t)blockIdx.x * blockDim.x + threadIdx.x;
    size_t stride = (size_t)gridDim.x * blockDim.x;
    const size_t slot0_4 = (size_t)2 * UU * NB / 4;          // 4096 float4
    const size_t total_4 = (size_t)HSEQ_SLOTS * 2 * UU * NB / 4;
    uint4 can4 = make_uint4(CANARY, CANARY, CANARY, CANARY);
    float4* h4 = (float4*)g_hseq;
    for (size_t i = idx; i < total_4; i += stride) {
        if (i < slot0_4) {
            h4[i] = zero_init ? make_float4(0.f, 0.f, 0.f, 0.f)
                              : ((const float4*)&g_stateH[0][0])[i];
        } else {
            ((uint4*)h4)[i] = can4;
        }
    }
    if (zero_init) {
        float4* c4 = (float4*)&g_stateC[0][0];
        for (size_t i = idx; i < slot0_4; i += stride)
            c4[i] = make_float4(0.f, 0.f, 0.f, 0.f);
    }
}

// ---------------- recurrent kernel: self-timed dataflow ----------------
// 128 CTAs (64/dir) x 256 threads. warp = 32-k chunk, lane = batch.
// h published via canary-initialized per-step slots; consumers poll data directly.
// No global barrier, no atomics, no fences.
#define RECUR_SMEM (16384 + 32768)
__global__ void __launch_bounds__(256, 1)
recur_kernel(const float* __restrict__ x0, float* __restrict__ dout,
             int layer, int is_last, int wstates) {
    extern __shared__ __align__(16) unsigned char smraw[];
    ulonglong2* U4s = (ulonglong2*)smraw;                  // [k][unit] (if,go) 16KB
    ulonglong2* red2 = (ulonglong2*)(smraw + 16384);       // [2][32*32]        32KB

    const int cta = blockIdx.x;
    const int dir = cta >> 6;
    const int uq = cta & 63;
    const int tid = threadIdx.x;
    const int w = tid >> 5;       // k-chunk / consumer group
    const int b = tid & 31;       // batch lane

    // stage U slice: per k, 4 units x (if,go) float4
    {
        const float* Up = g_Ure[layer][dir];
        for (int i = tid; i < 1024; i += 256) {
            int k = i >> 2, u = i & 3;
            float4 v = *(const float4*)&Up[(size_t)k * 1024 + (uq * 4 + u) * 4];
            *(float4*)&U4s[k * 4 + u] = v;
        }
    }

    const int ur = tid >> 5;          // reducer unit (tid < 128)
    const int br = tid & 31;
    float4 w0v = make_float4(0.f, 0.f, 0.f, 0.f), b0v = w0v;
    float c = 0.0f;
    if (tid < 128) {
        if (layer == 0) {
            w0v = *(const float4*)&g_W0re[dir][(uq * 4 + ur) * 4];
            b0v = *(const float4*)&g_b0re[dir][(uq * 4 + ur) * 4];
        }
        c = g_stateC[dir][(uq * 4 + ur) * 32 + br];
    }

    float* xout = is_last ? dout : (layer == 0 ? g_X1 : g_X2);
    const float* xzbase = g_xz + dir * 1024 + uq * 16 + ur * 4;

    __syncthreads();

    for (int s = 0; s < TT; ++s) {
        const int t = dir ? (TT - 1 - s) : s;

        // reducers prefetch input preacts (overlaps with the h poll)
        float4 xzv = make_float4(0.f, 0.f, 0.f, 0.f);
        if (tid < 128) {
            if (layer == 0) {
                float xv = __ldg(&x0[(size_t)br * TT + t]);
                xzv.x = fmaf(xv, w0v.x, b0v.x);
                xzv.y = fmaf(xv, w0v.y, b0v.y);
                xzv.z = fmaf(xv, w0v.z, b0v.z);
                xzv.w = fmaf(xv, w0v.w, b0v.w);
            } else {
                xzv = __ldg((const float4*)(xzbase + ((size_t)t * NB + br) * 2048));
            }
        }

        // load this warp's 32 h values from slot s; re-poll any canary entries
        const float* hrow = g_hseq + ((size_t)s * 2 + dir) * (UU * NB)
                            + (w * 32) * 32 + b;
        unsigned rv[32];
#pragma unroll
        for (int kk = 0; kk < 32; ++kk)
            rv[kk] = ld_relax(hrow + kk * 32);
#pragma unroll
        for (int kk = 0; kk < 32; ++kk)
            while (rv[kk] == CANARY) rv[kk] = ld_relax(hrow + kk * 32);

        // partial gate sums over this warp's 32-k slice, all 4 units
        unsigned long long acc[4][2];
#pragma unroll
        for (int u = 0; u < 4; ++u) { acc[u][0] = 0ULL; acc[u][1] = 0ULL; }
        {
            const ulonglong2* up = &U4s[(w * 32) * 4];
#pragma unroll
            for (int kk = 0; kk < 32; ++kk) {
                unsigned long long h2 = pack2(__uint_as_float(rv[kk]));
                ulonglong2 u0 = up[kk * 4 + 0];
                ulonglong2 u1 = up[kk * 4 + 1];
                ulonglong2 u2 = up[kk * 4 + 2];
                ulonglong2 u3 = up[kk * 4 + 3];
                fma2(acc[0][0], h2, u0.x); fma2(acc[0][1], h2, u0.y);
                fma2(acc[1][0], h2, u1.x); fma2(acc[1][1], h2, u1.y);
                fma2(acc[2][0], h2, u2.x); fma2(acc[2][1], h2, u2.y);
                fma2(acc[3][0], h2, u3.x); fma2(acc[3][1], h2, u3.y);
            }
        }
        ulonglong2* rbuf = red2 + (s & 1) * 1024;
#pragma unroll
        for (int u = 0; u < 4; ++u) {
            ulonglong2 pv; pv.x = acc[u][0]; pv.y = acc[u][1];
            rbuf[(w * 4 + u) * 32 + b] = pv;
        }
        __syncthreads();

        if (tid < 128) {
            unsigned long long aif = pack2b(xzv.x, xzv.y);
            unsigned long long ago = pack2b(xzv.z, xzv.w);
#pragma unroll
            for (int w2 = 0; w2 < 8; ++w2) {
                ulonglong2 pv = rbuf[(w2 * 4 + ur) * 32 + br];
                add2(aif, pv.x);
                add2(ago, pv.y);
            }
            float2 fif = unpack2(aif), fgo = unpack2(ago);
            float zi = fif.x, zf = fif.y, zg = fgo.x, zo = fgo.y;

            c = sig_p(zf) * c + sig_p(zi) * tanh_p(zg);
            float h = sig_p(zo) * tanh_p(c);

            const int u = uq * 4 + ur;
            // publish h into slot s+1 (data-as-flag; single relaxed store)
            st_relax(g_hseq + ((size_t)(s + 1) * 2 + dir) * (UU * NB) + u * 32 + br, h);

            if (is_last)
                dout[((size_t)br * TT + t) * 512 + dir * 256 + u] = h;
            else
                xout[((size_t)t * NB + br) * 512 + dir * 256 + u] = h;

            if (s == TT - 1) {
                g_stateH[dir][u * 32 + br] = h;
                g_stateC[dir][u * 32 + br] = c;
                if (is_last && wstates) {
                    float* tail = dout + OUT_MAIN + (size_t)dir * 2 * NB * UU;
                    tail[br * UU + u] = h;
                    tail[NB * UU + br * UU + u] = c;
                }
            }
        }
    }
}

// ---------------- projection GEMM: C[65536,2048] = A[65536,512] @ W[512,2048] + bias ----
#define GBM 128
#define GBN 128
#define GBK 16
#define AS_LD 264
#define AS_BUF (GBK * AS_LD)
#define WS_BUF (GBK * GBN)
#define GEMM_SMEM ((2 * AS_BUF + 2 * WS_BUF) * 4)

__global__ void __launch_bounds__(256, 2)
gemm_kernel(int l) {
    extern __shared__ __align__(16) float gsm[];
    float* As = gsm;
    float* Ws = gsm + 2 * AS_BUF;

    const float* A = (l == 0) ? g_X1 : g_X2;
    const float* W = g_Wcat[l];
    const float* bias = g_bcat[l];
    float* C = g_xz;

    const int n0 = blockIdx.x * GBN;
    const int r0 = blockIdx.y * GBM;
    const int tid = threadIdx.x;
    const int tx = tid & 15;
    const int ty = tid >> 4;

    const int arow = tid >> 2;
    const int akq = tid & 3;
    const int wk = tid >> 5;
    const int wn = tid & 31;

    unsigned long long acc[8][4];
#pragma unroll
    for (int i = 0; i < 8; ++i)
#pragma unroll
        for (int j = 0; j < 4; ++j) acc[i][j] = 0ULL;

    const float* Ag = A + (size_t)(r0 + arow) * 512 + akq * 4;
    const float* Wg = W + (size_t)wk * 2048 + n0 + wn * 4;

    float4 ra0[2], ra1[2], rw0[2], rw1[2];
#pragma unroll
    for (int p = 0; p < 2; ++p) {
        ra0[p] = __ldg((const float4*)(Ag + p * 16));
        ra1[p] = __ldg((const float4*)(Ag + (size_t)64 * 512 + p * 16));
        rw0[p] = __ldg((const float4*)(Wg + (size_t)p * 16 * 2048));
        rw1[p] = __ldg((const float4*)(Wg + (size_t)p * 16 * 2048 + (size_t)8 * 2048));
    }

    for (int kt = 0; kt < 32; ++kt) {
        const int pp = kt & 1;
        float* as = As + pp * AS_BUF;
        float* ws = Ws + pp * WS_BUF;

        {
            float* d0 = as + (akq * 4 + 0) * AS_LD;
            float* d1 = as + (akq * 4 + 1) * AS_LD;
            float* d2 = as + (akq * 4 + 2) * AS_LD;
            float* d3 = as + (akq * 4 + 3) * AS_LD;
            int m0 = 2 * arow, m1 = 2 * (arow + 64);
            float4 a0 = ra0[pp], a1 = ra1[pp];
            d0[m0] = a0.x; d0[m0 + 1] = a0.x; d0[m1] = a1.x; d0[m1 + 1] = a1.x;
            d1[m0] = a0.y; d1[m0 + 1] = a0.y; d1[m1] = a1.y; d1[m1 + 1] = a1.y;
            d2[m0] = a0.z; d2[m0 + 1] = a0.z; d2[m1] = a1.z; d2[m1 + 1] = a1.z;
            d3[m0] = a0.w; d3[m0 + 1] = a0.w; d3[m1] = a1.w; d3[m1 + 1] = a1.w;
        }
        *(float4*)&ws[wk * GBN + wn * 4] = rw0[pp];
        *(float4*)&ws[(wk + 8) * GBN + wn * 4] = rw1[pp];
        __syncthreads();

        if (kt < 30) {
            ra0[pp] = __ldg((const float4*)(Ag + (kt + 2) * 16));
            ra1[pp] = __ldg((const float4*)(Ag + (size_t)64 * 512 + (kt + 2) * 16));
            rw0[pp] = __ldg((const float4*)(Wg + (size_t)(kt + 2) * 16 * 2048));
            rw1[pp] = __ldg((const float4*)(Wg + (size_t)(kt + 2) * 16 * 2048 + (size_t)8 * 2048));
        }

#pragma unroll
        for (int k = 0; k < GBK; ++k) {
            const float* ar = as + k * AS_LD + ty * 16;
            ulonglong2 a01 = *(const ulonglong2*)(ar);
            ulonglong2 a23 = *(const ulonglong2*)(ar + 4);
            ulonglong2 a45 = *(const ulonglong2*)(ar + 8);
            ulonglong2 a67 = *(const ulonglong2*)(ar + 12);
            const unsigned long long* wr =
                (const unsigned long long*)(ws + k * GBN + tx * 8);
            ulonglong2 w01 = *(const ulonglong2*)(wr);
            ulonglong2 w23 = *(const ulonglong2*)(wr + 2);

            unsigned long long am[8] = {a01.x, a01.y, a23.x, a23.y,
                                        a45.x, a45.y, a67.x, a67.y};
            unsigned long long wp[4] = {w01.x, w01.y, w23.x, w23.y};
#pragma unroll
            for (int m = 0; m < 8; ++m)
#pragma unroll
                for (int j = 0; j < 4; ++j) fma2(acc[m][j], am[m], wp[j]);
        }
        __syncthreads();
    }

    float4 bv0 = *(const float4*)&bias[n0 + tx * 8];
    float4 bv1 = *(const float4*)&bias[n0 + tx * 8 + 4];
#pragma unroll
    for (int m = 0; m < 8; ++m) {
        int row = r0 + ty * 8 + m;
        float2 p0 = unpack2(acc[m][0]);
        float2 p1 = unpack2(acc[m][1]);
        float2 p2 = unpack2(acc[m][2]);
        float2 p3 = unpack2(acc[m][3]);
        float4 o0 = make_float4(p0.x + bv0.x, p0.y + bv0.y, p1.x + bv0.z, p1.y + bv0.w);
        float4 o1 = make_float4(p2.x + bv1.x, p2.y + bv1.y, p3.x + bv1.z, p3.y + bv1.w);
        float* cp = &C[(size_t)row * 2048 + n0 + tx * 8];
        *(float4*)cp = o0;
        *(float4*)(cp + 4) = o1;
    }
}

// ---------------- launch ----------------
extern "C" void kernel_launch(void* const* d_in, const int* in_sizes, int n_in,
                              void* d_out, int out_size) {
    const float* inputs = (const float*)d_in[0];
    const float* W0f = (const float*)d_in[1];
    const float* U0f = (const float*)d_in[2];
    const float* b0f = (const float*)d_in[3];
    const float* W0b = (const float*)d_in[4];
    const float* U0b = (const float*)d_in[5];
    const float* b0b = (const float*)d_in[6];
    const float* Wf = (const float*)d_in[7];
    const float* Uf = (const float*)d_in[8];
    const float* bf = (const float*)d_in[9];
    const float* Wb = (const float*)d_in[10];
    const float* Ub = (const float*)d_in[11];
    const float* bb = (const float*)d_in[12];
    float* out = (float*)d_out;

    int wstates = ((size_t)out_size >= OUT_FULL) ? 1 : 0;

    cudaFuncSetAttribute(recur_kernel, cudaFuncAttributeMaxDynamicSharedMemorySize,
                         RECUR_SMEM);
    cudaFuncSetAttribute(gemm_kernel, cudaFuncAttributeMaxDynamicSharedMemorySize,
                         GEMM_SMEM);
    cudaFuncSetAttribute(gemm_kernel, cudaFuncAttributePreferredSharedMemoryCarveout,
                         100);

    prep_kernel<<<512, 256>>>(W0f, U0f, b0f, W0b, U0b, b0b, Wf, Uf, bf, Wb, Ub, bb);

    // layer 0
    pre_recur_kernel<<<1024, 256>>>(1);
    recur_kernel<<<128, 256, RECUR_SMEM>>>(inputs, out, 0, 0, 0);

    // layer 1
    gemm_kernel<<<dim3(16, 512), 256, GEMM_SMEM>>>(0);
    pre_recur_kernel<<<1024, 256>>>(0);
    recur_kernel<<<128, 256, RECUR_SMEM>>>(nullptr, out, 1, 0, 0);

    // layer 2
    gemm_kernel<<<dim3(16, 512), 256, GEMM_SMEM>>>(1);
    pre_recur_kernel<<<1024, 256>>>(0);
    recur_kernel<<<128, 256, RECUR_SMEM>>>(nullptr, out, 2, 1, wstates);
}

// round 12
// speedup vs baseline: 2.4984x; 2.4984x over previous
#include <cuda_runtime.h>
#include <cuda_bf16.h>
#include <cstdint>
#include <cstddef>

// Problem dims
#define TT 2048
#define NB 32
#define UU 256
#define OUT_MAIN ((size_t)NB * TT * 512)
#define OUT_FULL (OUT_MAIN + 4 * (size_t)NB * UU)

// ---------------- static device scratch ----------------
__device__ float g_xz[(size_t)TT * NB * 2048];   // [t*32+b][2048] gate preacts
__device__ float g_X1[(size_t)TT * NB * 512];    // layer0 output [t][b][512]
__device__ float g_X2[(size_t)TT * NB * 512];    // layer1 output
__device__ float g_Ure[3][2][UU * 1024];         // [layer][dir][k][u*4+g]
__device__ float g_Wcat[2][512 * 2048];          // [l][k][d*1024 + u*4+g]
__device__ float g_bcat[2][2048];
__device__ float g_W0re[2][1024];
__device__ float g_b0re[2][1024];
__device__ float g_hbuf[2][2][UU * NB];          // [phase][dir][k*32+b]
__device__ float g_stateH[2][UU * NB];
__device__ float g_stateC[2][UU * NB];
__device__ unsigned g_cnt[2];

// ---------------- packed f32x2 helpers ----------------
__device__ __forceinline__ void fma2(unsigned long long& d, unsigned long long a,
                                     unsigned long long b) {
    asm("fma.rn.f32x2 %0, %1, %2, %0;" : "+l"(d) : "l"(a), "l"(b));
}
__device__ __forceinline__ void add2(unsigned long long& d, unsigned long long a) {
    asm("add.rn.f32x2 %0, %0, %1;" : "+l"(d) : "l"(a));
}
__device__ __forceinline__ unsigned long long pack2(float x) {
    unsigned long long r;
    asm("mov.b64 %0, {%1, %1};" : "=l"(r) : "f"(x));
    return r;
}
__device__ __forceinline__ unsigned long long pack2b(float x, float y) {
    unsigned long long r;
    asm("mov.b64 %0, {%1, %2};" : "=l"(r) : "f"(x), "f"(y));
    return r;
}
__device__ __forceinline__ float2 unpack2(unsigned long long v) {
    float2 f;
    asm("mov.b64 {%0, %1}, %2;" : "=f"(f.x), "=f"(f.y) : "l"(v));
    return f;
}

// ---------------- fast-math-immune activations ----------------
__device__ __forceinline__ float exp_p(float x) {
    float t = fminf(fmaxf(x, -87.0f), 87.0f);
    float n = rintf(t * 1.4426950408889634f);
    float f = fmaf(n, -0.693145751953125f, t);
    f = fmaf(n, -1.4286067653e-06f, f);
    float p = 1.9841270e-04f;
    p = fmaf(p, f, 1.3888889e-03f);
    p = fmaf(p, f, 8.3333333e-03f);
    p = fmaf(p, f, 4.1666668e-02f);
    p = fmaf(p, f, 1.6666667e-01f);
    p = fmaf(p, f, 0.5f);
    p = fmaf(p, f, 1.0f);
    p = fmaf(p, f, 1.0f);
    int ni = (int)n;
    float sc = __int_as_float((ni + 127) << 23);
    return p * sc;
}
__device__ __forceinline__ float rcp_nr(float d) {
    float r;
    asm("rcp.approx.f32 %0, %1;" : "=f"(r) : "f"(d));
    r = fmaf(r, fmaf(-d, r, 1.0f), r);
    return r;
}
__device__ __forceinline__ float sig_p(float x) {
    return rcp_nr(1.0f + exp_p(-x));
}
__device__ __forceinline__ float tanh_p(float x) {
    float a = fabsf(x);
    float e = exp_p(-2.0f * a);
    float r = (1.0f - e) * rcp_nr(1.0f + e);
    return copysignf(r, x);
}

// ---------------- weight rearrangement ----------------
__global__ void prep_kernel(const float* __restrict__ W0f, const float* __restrict__ U0f,
                            const float* __restrict__ b0f, const float* __restrict__ W0b,
                            const float* __restrict__ U0b, const float* __restrict__ b0b,
                            const float* __restrict__ Wf, const float* __restrict__ Uf,
                            const float* __restrict__ bf, const float* __restrict__ Wb,
                            const float* __restrict__ Ub, const float* __restrict__ bb) {
    int idx0 = blockIdx.x * blockDim.x + threadIdx.x;
    int stride = gridDim.x * blockDim.x;
    for (int i = idx0; i < 3 * 2 * 256 * 1024; i += stride) {
        int j = i & 1023;
        int k = (i >> 10) & 255;
        int d = (i >> 18) & 1;
        int l = i >> 19;
        int u = j >> 2, g = j & 3;
        const float* Us = (l == 0) ? (d ? U0b : U0f)
                                   : (d ? Ub + (size_t)(l - 1) * 256 * 1024
                                        : Uf + (size_t)(l - 1) * 256 * 1024);
        g_Ure[l][d][k * 1024 + j] = Us[k * 1024 + g * 256 + u];
    }
    for (int i = idx0; i < 2 * 512 * 2048; i += stride) {
        int j2 = i & 2047;
        int k = (i >> 11) & 511;
        int l = i >> 20;
        int d = j2 >> 10;
        int j = j2 & 1023;
        int u = j >> 2, g = j & 3;
        const float* Ws = d ? Wb : Wf;
        g_Wcat[l][k * 2048 + j2] = Ws[(size_t)l * 512 * 1024 + k * 1024 + g * 256 + u];
    }
    for (int i = idx0; i < 2 * 2048; i += stride) {
        int j2 = i & 2047;
        int l = i >> 11;
        int d = j2 >> 10;
        int j = j2 & 1023;
        int u = j >> 2, g = j & 3;
        const float* bs = d ? bb : bf;
        g_bcat[l][j2] = bs[l * 1024 + g * 256 + u];
    }
    for (int i = idx0; i < 2 * 1024; i += stride) {
        int j = i & 1023;
        int d = i >> 10;
        int u = j >> 2, g = j & 3;
        g_W0re[d][j] = (d ? W0b : W0f)[g * 256 + u];
        g_b0re[d][j] = (d ? b0b : b0f)[g * 256 + u];
    }
}

// ---------------- per-layer init ----------------
__global__ void pre_recur_kernel(int zero_init) {
    int idx = blockIdx.x * blockDim.x + threadIdx.x;
    int stride = gridDim.x * blockDim.x;
    if (idx < 2) g_cnt[idx] = 0;
    float* hb = &g_hbuf[0][0][0];
    const float* sh = &g_stateH[0][0];
    float* sc = &g_stateC[0][0];
    for (int i = idx; i < 2 * UU * NB; i += stride) {
        hb[i] = zero_init ? 0.0f : sh[i];
        if (zero_init) sc[i] = 0.0f;
    }
}

// ---------------- recurrent kernel: both directions per CTA ----------------
// 128 CTAs x 256 threads. warps 0-3 = fwd (64-k chunk each), warps 4-7 = bwd.
// Each SMSP gets 1 fwd + 1 bwd warp: while one direction sits in its sync
// chain, the other owns the FMA pipes. Per-dir counters, bars, smem buffers.
__global__ void __launch_bounds__(256, 1)
recur_kernel(const float* __restrict__ x0, float* __restrict__ dout,
             int layer, int is_last, int wstates) {
    __shared__ __align__(16) ulonglong2 U4s[2 * UU * 2];        // [d][k][uu] 16KB
    __shared__ __align__(16) ulonglong2 red2[2][2][4 * 2 * 32]; // [d][par][wd*2+uu][b] 16KB

    const int up = blockIdx.x;        // unit pair 0..127 -> units up*2, up*2+1
    const int tid = threadIdx.x;
    const int dir = tid >> 7;
    const int td = tid & 127;
    const int wd = td >> 5;           // k-chunk within dir (64 k each)
    const int b = tid & 31;           // batch lane

    // stage U for both dirs: flat i = d*512 + k*2 + uu
    {
        const float* U0 = g_Ure[layer][0];
        const float* U1 = g_Ure[layer][1];
        for (int i = tid; i < 1024; i += 256) {
            int d = i >> 9, k = (i >> 1) & 255, uu = i & 1;
            const float* Up = d ? U1 : U0;
            float4 v = *(const float4*)&Up[(size_t)k * 1024 + (up * 2 + uu) * 4];
            *(float4*)&U4s[i] = v;
        }
    }

    // reducer role: td < 64 -> (ur, br)
    const int ur = td >> 5;           // unit within pair (valid for td < 64)
    const int br = td & 31;
    float4 w0v = make_float4(0.f, 0.f, 0.f, 0.f), b0v = w0v;
    float c = 0.0f;
    if (td < 64) {
        if (layer == 0) {
            w0v = *(const float4*)&g_W0re[dir][(up * 2 + ur) * 4];
            b0v = *(const float4*)&g_b0re[dir][(up * 2 + ur) * 4];
        }
        c = g_stateC[dir][(up * 2 + ur) * 32 + br];
    }

    float* xout = is_last ? dout : (layer == 0 ? g_X1 : g_X2);
    unsigned* cntp = &g_cnt[dir];
    const float* xzbase = g_xz + dir * 1024 + (up * 2 + ur) * 4;

    __syncthreads();

    for (int s = 0; s < TT; ++s) {
        const int t = dir ? (TT - 1 - s) : s;

        // reducers prefetch input preacts (overlaps the poll)
        float4 xzv = make_float4(0.f, 0.f, 0.f, 0.f);
        if (td < 64) {
            if (layer == 0) {
                float xv = __ldg(&x0[(size_t)br * TT + t]);
                xzv.x = fmaf(xv, w0v.x, b0v.x);
                xzv.y = fmaf(xv, w0v.y, b0v.y);
                xzv.z = fmaf(xv, w0v.z, b0v.z);
                xzv.w = fmaf(xv, w0v.w, b0v.w);
            } else {
                xzv = __ldg((const float4*)(xzbase + ((size_t)t * NB + br) * 2048));
            }
        }

        // every thread of this dir polls (one L2 request per warp, no bar wake)
        if (s > 0) {
            const unsigned target = (unsigned)(128 * s);
            unsigned v;
            do {
                asm volatile("ld.acquire.gpu.global.u32 %0, [%1];"
                             : "=r"(v) : "l"(cntp) : "memory");
            } while (v < target);
        }

        // this warp's 64-k chunk, 2 halves of 32 to bound registers
        unsigned long long a00 = 0ULL, a01 = 0ULL, a10 = 0ULL, a11 = 0ULL;
        const float* hrow = &g_hbuf[s & 1][dir][0] + (wd * 64) * 32 + b;
        const ulonglong2* ub = &U4s[dir * 512 + (wd * 64) * 2];
#pragma unroll
        for (int half = 0; half < 2; ++half) {
            float hr[32];
#pragma unroll
            for (int kk = 0; kk < 32; ++kk)
                hr[kk] = __ldcg(hrow + (half * 32 + kk) * 32);
            const ulonglong2* up_ = ub + half * 64;
#pragma unroll
            for (int kk = 0; kk < 32; ++kk) {
                unsigned long long h2 = pack2(hr[kk]);
                ulonglong2 uv0 = up_[kk * 2 + 0];
                ulonglong2 uv1 = up_[kk * 2 + 1];
                fma2(a00, h2, uv0.x); fma2(a01, h2, uv0.y);
                fma2(a10, h2, uv1.x); fma2(a11, h2, uv1.y);
            }
        }
        ulonglong2* rb = red2[dir][s & 1];
        {
            ulonglong2 p0; p0.x = a00; p0.y = a01;
            ulonglong2 p1; p1.x = a10; p1.y = a11;
            rb[(wd * 2 + 0) * 32 + b] = p0;
            rb[(wd * 2 + 1) * 32 + b] = p1;
        }
        // per-direction barrier (128 threads)
        if (dir == 0) asm volatile("bar.sync 1, 128;" ::: "memory");
        else          asm volatile("bar.sync 2, 128;" ::: "memory");

        if (td < 64) {
            unsigned long long aif = pack2b(xzv.x, xzv.y);
            unsigned long long ago = pack2b(xzv.z, xzv.w);
#pragma unroll
            for (int w2 = 0; w2 < 4; ++w2) {
                ulonglong2 pv = rb[(w2 * 2 + ur) * 32 + br];
                add2(aif, pv.x);
                add2(ago, pv.y);
            }
            float2 fif = unpack2(aif), fgo = unpack2(ago);
            float zi = fif.x, zf = fif.y, zg = fgo.x, zo = fgo.y;

            c = sig_p(zf) * c + sig_p(zi) * tanh_p(zg);
            float h = sig_p(zo) * tanh_p(c);

            const int u = up * 2 + ur;
            g_hbuf[(s + 1) & 1][dir][u * 32 + br] = h;
            // reducer-only barrier (64 threads), then release
            if (dir == 0) asm volatile("bar.sync 3, 64;" ::: "memory");
            else          asm volatile("bar.sync 4, 64;" ::: "memory");
            if (td == 0) {
                asm volatile("red.release.gpu.global.add.u32 [%0], %1;"
                             :: "l"(cntp), "r"(1u) : "memory");
            }

            if (is_last)
                dout[((size_t)br * TT + t) * 512 + dir * 256 + u] = h;
            else
                xout[((size_t)t * NB + br) * 512 + dir * 256 + u] = h;

            if (s == TT - 1) {
                g_stateH[dir][u * 32 + br] = h;
                g_stateC[dir][u * 32 + br] = c;
                if (is_last && wstates) {
                    float* tail = dout + OUT_MAIN + (size_t)dir * 2 * NB * UU;
                    tail[br * UU + u] = h;
                    tail[NB * UU + br * UU + u] = c;
                }
            }
        }
    }
}

// ---------------- projection GEMM: C[65536,2048] = A[65536,512] @ W[512,2048] + bias ----
#define GBM 128
#define GBN 128
#define GBK 16
#define AS_LD 264
#define AS_BUF (GBK * AS_LD)
#define WS_BUF (GBK * GBN)
#define GEMM_SMEM ((2 * AS_BUF + 2 * WS_BUF) * 4)

__global__ void __launch_bounds__(256, 2)
gemm_kernel(int l) {
    extern __shared__ __align__(16) float gsm[];
    float* As = gsm;
    float* Ws = gsm + 2 * AS_BUF;

    const float* A = (l == 0) ? g_X1 : g_X2;
    const float* W = g_Wcat[l];
    const float* bias = g_bcat[l];
    float* C = g_xz;

    const int n0 = blockIdx.x * GBN;
    const int r0 = blockIdx.y * GBM;
    const int tid = threadIdx.x;
    const int tx = tid & 15;
    const int ty = tid >> 4;

    const int arow = tid >> 2;
    const int akq = tid & 3;
    const int wk = tid >> 5;
    const int wn = tid & 31;

    unsigned long long acc[8][4];
#pragma unroll
    for (int i = 0; i < 8; ++i)
#pragma unroll
        for (int j = 0; j < 4; ++j) acc[i][j] = 0ULL;

    const float* Ag = A + (size_t)(r0 + arow) * 512 + akq * 4;
    const float* Wg = W + (size_t)wk * 2048 + n0 + wn * 4;

    float4 ra0[2], ra1[2], rw0[2], rw1[2];
#pragma unroll
    for (int p = 0; p < 2; ++p) {
        ra0[p] = __ldg((const float4*)(Ag + p * 16));
        ra1[p] = __ldg((const float4*)(Ag + (size_t)64 * 512 + p * 16));
        rw0[p] = __ldg((const float4*)(Wg + (size_t)p * 16 * 2048));
        rw1[p] = __ldg((const float4*)(Wg + (size_t)p * 16 * 2048 + (size_t)8 * 2048));
    }

    for (int kt = 0; kt < 32; ++kt) {
        const int pp = kt & 1;
        float* as = As + pp * AS_BUF;
        float* ws = Ws + pp * WS_BUF;

        {
            float* d0 = as + (akq * 4 + 0) * AS_LD;
            float* d1 = as + (akq * 4 + 1) * AS_LD;
            float* d2 = as + (akq * 4 + 2) * AS_LD;
            float* d3 = as + (akq * 4 + 3) * AS_LD;
            int m0 = 2 * arow, m1 = 2 * (arow + 64);
            float4 a0 = ra0[pp], a1 = ra1[pp];
            d0[m0] = a0.x; d0[m0 + 1] = a0.x; d0[m1] = a1.x; d0[m1 + 1] = a1.x;
            d1[m0] = a0.y; d1[m0 + 1] = a0.y; d1[m1] = a1.y; d1[m1 + 1] = a1.y;
            d2[m0] = a0.z; d2[m0 + 1] = a0.z; d2[m1] = a1.z; d2[m1 + 1] = a1.z;
            d3[m0] = a0.w; d3[m0 + 1] = a0.w; d3[m1] = a1.w; d3[m1 + 1] = a1.w;
        }
        *(float4*)&ws[wk * GBN + wn * 4] = rw0[pp];
        *(float4*)&ws[(wk + 8) * GBN + wn * 4] = rw1[pp];
        __syncthreads();

        if (kt < 30) {
            ra0[pp] = __ldg((const float4*)(Ag + (kt + 2) * 16));
            ra1[pp] = __ldg((const float4*)(Ag + (size_t)64 * 512 + (kt + 2) * 16));
            rw0[pp] = __ldg((const float4*)(Wg + (size_t)(kt + 2) * 16 * 2048));
            rw1[pp] = __ldg((const float4*)(Wg + (size_t)(kt + 2) * 16 * 2048 + (size_t)8 * 2048));
        }

#pragma unroll
        for (int k = 0; k < GBK; ++k) {
            const float* ar = as + k * AS_LD + ty * 16;
            ulonglong2 a01 = *(const ulonglong2*)(ar);
            ulonglong2 a23 = *(const ulonglong2*)(ar + 4);
            ulonglong2 a45 = *(const ulonglong2*)(ar + 8);
            ulonglong2 a67 = *(const ulonglong2*)(ar + 12);
            const unsigned long long* wr =
                (const unsigned long long*)(ws + k * GBN + tx * 8);
            ulonglong2 w01 = *(const ulonglong2*)(wr);
            ulonglong2 w23 = *(const ulonglong2*)(wr + 2);

            unsigned long long am[8] = {a01.x, a01.y, a23.x, a23.y,
                                        a45.x, a45.y, a67.x, a67.y};
            unsigned long long wp[4] = {w01.x, w01.y, w23.x, w23.y};
#pragma unroll
            for (int m = 0; m < 8; ++m)
#pragma unroll
                for (int j = 0; j < 4; ++j) fma2(acc[m][j], am[m], wp[j]);
        }
        __syncthreads();
    }

    float4 bv0 = *(const float4*)&bias[n0 + tx * 8];
    float4 bv1 = *(const float4*)&bias[n0 + tx * 8 + 4];
#pragma unroll
    for (int m = 0; m < 8; ++m) {
        int row = r0 + ty * 8 + m;
        float2 p0 = unpack2(acc[m][0]);
        float2 p1 = unpack2(acc[m][1]);
        float2 p2 = unpack2(acc[m][2]);
        float2 p3 = unpack2(acc[m][3]);
        float4 o0 = make_float4(p0.x + bv0.x, p0.y + bv0.y, p1.x + bv0.z, p1.y + bv0.w);
        float4 o1 = make_float4(p2.x + bv1.x, p2.y + bv1.y, p3.x + bv1.z, p3.y + bv1.w);
        float* cp = &C[(size_t)row * 2048 + n0 + tx * 8];
        *(float4*)cp = o0;
        *(float4*)(cp + 4) = o1;
    }
}

// ---------------- launch ----------------
extern "C" void kernel_launch(void* const* d_in, const int* in_sizes, int n_in,
                              void* d_out, int out_size) {
    const float* inputs = (const float*)d_in[0];
    const float* W0f = (const float*)d_in[1];
    const float* U0f = (const float*)d_in[2];
    const float* b0f = (const float*)d_in[3];
    const float* W0b = (const float*)d_in[4];
    const float* U0b = (const float*)d_in[5];
    const float* b0b = (const float*)d_in[6];
    const float* Wf = (const float*)d_in[7];
    const float* Uf = (const float*)d_in[8];
    const float* bf = (const float*)d_in[9];
    const float* Wb = (const float*)d_in[10];
    const float* Ub = (const float*)d_in[11];
    const float* bb = (const float*)d_in[12];
    float* out = (float*)d_out;

    int wstates = ((size_t)out_size >= OUT_FULL) ? 1 : 0;

    cudaFuncSetAttribute(gemm_kernel, cudaFuncAttributeMaxDynamicSharedMemorySize,
                         GEMM_SMEM);
    cudaFuncSetAttribute(gemm_kernel, cudaFuncAttributePreferredSharedMemoryCarveout,
                         100);

    prep_kernel<<<512, 256>>>(W0f, U0f, b0f, W0b, U0b, b0b, Wf, Uf, bf, Wb, Ub, bb);

    // layer 0
    pre_recur_kernel<<<64, 256>>>(1);
    recur_kernel<<<128, 256>>>(inputs, out, 0, 0, 0);

    // layer 1
    gemm_kernel<<<dim3(16, 512), 256, GEMM_SMEM>>>(0);
    pre_recur_kernel<<<64, 256>>>(0);
    recur_kernel<<<128, 256>>>(nullptr, out, 1, 0, 0);

    // layer 2
    gemm_kernel<<<dim3(16, 512), 256, GEMM_SMEM>>>(1);
    pre_recur_kernel<<<64, 256>>>(0);
    recur_kernel<<<128, 256>>>(nullptr, out, 2, 1, wstates);
}

// round 13
// speedup vs baseline: 3.5153x; 1.4070x over previous
#include <cuda_runtime.h>
#include <cuda_bf16.h>
#include <cstdint>
#include <cstddef>

// Problem dims
#define TT 2048
#define NB 32
#define UU 256
#define OUT_MAIN ((size_t)NB * TT * 512)
#define OUT_FULL (OUT_MAIN + 4 * (size_t)NB * UU)

// ---------------- static device scratch ----------------
__device__ float g_xz[(size_t)TT * NB * 2048];   // [t*32+b][2048] gate preacts
__device__ float g_X1[(size_t)TT * NB * 512];    // layer0 output [t][b][512]
__device__ float g_X2[(size_t)TT * NB * 512];    // layer1 output
__device__ float g_Ure[3][2][UU * 1024];         // [layer][dir][k][u*4+g]
__device__ float g_Wcat[2][512 * 2048];          // [l][k][d*1024 + u*4+g]
__device__ float g_bcat[2][2048];
__device__ float g_W0re[2][1024];
__device__ float g_b0re[2][1024];
__device__ float g_hbuf[2][2][UU * NB];          // [phase][dir][k*32+b]
__device__ float g_stateH[2][UU * NB];
__device__ float g_stateC[2][UU * NB];
__device__ unsigned g_cntg[2 * 8 * 32];          // [dir][group] padded 128B

// ---------------- packed f32x2 helpers ----------------
__device__ __forceinline__ void fma2(unsigned long long& d, unsigned long long a,
                                     unsigned long long b) {
    asm("fma.rn.f32x2 %0, %1, %2, %0;" : "+l"(d) : "l"(a), "l"(b));
}
__device__ __forceinline__ void add2(unsigned long long& d, unsigned long long a) {
    asm("add.rn.f32x2 %0, %0, %1;" : "+l"(d) : "l"(a));
}
__device__ __forceinline__ unsigned long long pack2(float x) {
    unsigned long long r;
    asm("mov.b64 %0, {%1, %1};" : "=l"(r) : "f"(x));
    return r;
}
__device__ __forceinline__ unsigned long long pack2b(float x, float y) {
    unsigned long long r;
    asm("mov.b64 %0, {%1, %2};" : "=l"(r) : "f"(x), "f"(y));
    return r;
}
__device__ __forceinline__ float2 unpack2(unsigned long long v) {
    float2 f;
    asm("mov.b64 {%0, %1}, %2;" : "=f"(f.x), "=f"(f.y) : "l"(v));
    return f;
}

// ---------------- fast-math-immune activations ----------------
__device__ __forceinline__ float exp_p(float x) {
    float t = fminf(fmaxf(x, -87.0f), 87.0f);
    float n = rintf(t * 1.4426950408889634f);
    float f = fmaf(n, -0.693145751953125f, t);
    f = fmaf(n, -1.4286067653e-06f, f);
    float p = 1.9841270e-04f;
    p = fmaf(p, f, 1.3888889e-03f);
    p = fmaf(p, f, 8.3333333e-03f);
    p = fmaf(p, f, 4.1666668e-02f);
    p = fmaf(p, f, 1.6666667e-01f);
    p = fmaf(p, f, 0.5f);
    p = fmaf(p, f, 1.0f);
    p = fmaf(p, f, 1.0f);
    int ni = (int)n;
    float sc = __int_as_float((ni + 127) << 23);
    return p * sc;
}
__device__ __forceinline__ float rcp_nr(float d) {
    float r;
    asm("rcp.approx.f32 %0, %1;" : "=f"(r) : "f"(d));
    r = fmaf(r, fmaf(-d, r, 1.0f), r);
    return r;
}
__device__ __forceinline__ float sig_p(float x) {
    return rcp_nr(1.0f + exp_p(-x));
}
__device__ __forceinline__ float tanh_p(float x) {
    float a = fabsf(x);
    float e = exp_p(-2.0f * a);
    float r = (1.0f - e) * rcp_nr(1.0f + e);
    return copysignf(r, x);
}

// ---------------- weight rearrangement ----------------
__global__ void prep_kernel(const float* __restrict__ W0f, const float* __restrict__ U0f,
                            const float* __restrict__ b0f, const float* __restrict__ W0b,
                            const float* __restrict__ U0b, const float* __restrict__ b0b,
                            const float* __restrict__ Wf, const float* __restrict__ Uf,
                            const float* __restrict__ bf, const float* __restrict__ Wb,
                            const float* __restrict__ Ub, const float* __restrict__ bb) {
    int idx0 = blockIdx.x * blockDim.x + threadIdx.x;
    int stride = gridDim.x * blockDim.x;
    for (int i = idx0; i < 3 * 2 * 256 * 1024; i += stride) {
        int j = i & 1023;
        int k = (i >> 10) & 255;
        int d = (i >> 18) & 1;
        int l = i >> 19;
        int u = j >> 2, g = j & 3;
        const float* Us = (l == 0) ? (d ? U0b : U0f)
                                   : (d ? Ub + (size_t)(l - 1) * 256 * 1024
                                        : Uf + (size_t)(l - 1) * 256 * 1024);
        g_Ure[l][d][k * 1024 + j] = Us[k * 1024 + g * 256 + u];
    }
    for (int i = idx0; i < 2 * 512 * 2048; i += stride) {
        int j2 = i & 2047;
        int k = (i >> 11) & 511;
        int l = i >> 20;
        int d = j2 >> 10;
        int j = j2 & 1023;
        int u = j >> 2, g = j & 3;
        const float* Ws = d ? Wb : Wf;
        g_Wcat[l][k * 2048 + j2] = Ws[(size_t)l * 512 * 1024 + k * 1024 + g * 256 + u];
    }
    for (int i = idx0; i < 2 * 2048; i += stride) {
        int j2 = i & 2047;
        int l = i >> 11;
        int d = j2 >> 10;
        int j = j2 & 1023;
        int u = j >> 2, g = j & 3;
        const float* bs = d ? bb : bf;
        g_bcat[l][j2] = bs[l * 1024 + g * 256 + u];
    }
    for (int i = idx0; i < 2 * 1024; i += stride) {
        int j = i & 1023;
        int d = i >> 10;
        int u = j >> 2, g = j & 3;
        g_W0re[d][j] = (d ? W0b : W0f)[g * 256 + u];
        g_b0re[d][j] = (d ? b0b : b0f)[g * 256 + u];
    }
}

// ---------------- per-layer init ----------------
__global__ void pre_recur_kernel(int zero_init) {
    int idx = blockIdx.x * blockDim.x + threadIdx.x;
    int stride = gridDim.x * blockDim.x;
    for (int i = idx; i < 2 * 8 * 32; i += stride) g_cntg[i] = 0;
    float* hb = &g_hbuf[0][0][0];
    const float* sh = &g_stateH[0][0];
    float* sc = &g_stateC[0][0];
    for (int i = idx; i < 2 * UU * NB; i += stride) {
        hb[i] = zero_init ? 0.0f : sh[i];
        if (zero_init) sc[i] = 0.0f;
    }
}

// ---------------- recurrent kernel ----------------
// 128 CTAs (64/dir) x 256 threads. warp = 32-k chunk, lane = batch.
// Per-group counters: consumer warp w waits only on its 8 producer CTAs
// (group w), polls directly (no bar wake), proceeds alone.
__global__ void __launch_bounds__(256, 1)
recur_kernel(const float* __restrict__ x0, float* __restrict__ dout,
             int layer, int is_last, int wstates) {
    __shared__ __align__(16) ulonglong2 U4s[UU * 4];        // [k][unit] 16KB
    __shared__ __align__(16) ulonglong2 red2[2][32 * 32];   // [par][w*4+u][b] 32KB

    const int cta = blockIdx.x;
    const int dir = cta >> 6;
    const int uq = cta & 63;
    const int tid = threadIdx.x;
    const int w = tid >> 5;       // k-chunk / consumer group
    const int b = tid & 31;       // batch lane

    // stage U slice: per k, 4 units x (if,go) float4
    {
        const float* Up = g_Ure[layer][dir];
        for (int i = tid; i < 1024; i += 256) {
            int k = i >> 2, u = i & 3;
            float4 v = *(const float4*)&Up[(size_t)k * 1024 + (uq * 4 + u) * 4];
            *(float4*)&U4s[k * 4 + u] = v;
        }
    }

    const int ur = tid >> 5;          // reducer unit (tid < 128)
    const int br = tid & 31;
    float4 w0v = make_float4(0.f, 0.f, 0.f, 0.f), b0v = w0v;
    float c = 0.0f;
    if (tid < 128) {
        if (layer == 0) {
            w0v = *(const float4*)&g_W0re[dir][(uq * 4 + ur) * 4];
            b0v = *(const float4*)&g_b0re[dir][(uq * 4 + ur) * 4];
        }
        c = g_stateC[dir][(uq * 4 + ur) * 32 + br];
    }

    float* xout = is_last ? dout : (layer == 0 ? g_X1 : g_X2);
    unsigned* pollp = &g_cntg[(dir * 8 + w) * 32];        // this warp's group
    unsigned* relp = &g_cntg[(dir * 8 + (uq >> 3)) * 32]; // this CTA's group
    const float* xzbase = g_xz + dir * 1024 + uq * 16 + ur * 4;

    __syncthreads();

    for (int s = 0; s < TT; ++s) {
        const int t = dir ? (TT - 1 - s) : s;

        // reducers prefetch input preacts (in flight during the poll)
        float4 xzv = make_float4(0.f, 0.f, 0.f, 0.f);
        if (tid < 128) {
            if (layer == 0) {
                float xv = __ldg(&x0[(size_t)br * TT + t]);
                xzv.x = fmaf(xv, w0v.x, b0v.x);
                xzv.y = fmaf(xv, w0v.y, b0v.y);
                xzv.z = fmaf(xv, w0v.z, b0v.z);
                xzv.w = fmaf(xv, w0v.w, b0v.w);
            } else {
                xzv = __ldg((const float4*)(xzbase + ((size_t)t * NB + br) * 2048));
            }
        }

        // per-warp poll on this k-chunk's producer group (8 CTAs)
        if (s > 0) {
            const unsigned target = (unsigned)(8 * s);
            unsigned v;
            do {
                asm volatile("ld.acquire.gpu.global.u32 %0, [%1];"
                             : "=r"(v) : "l"(pollp) : "memory");
            } while (v < target);
        }

        // load this warp's 32 h values straight into registers (coalesced)
        float hr[32];
        {
            const float* hrow = &g_hbuf[s & 1][dir][(w * 32) * 32 + b];
#pragma unroll
            for (int kk = 0; kk < 32; ++kk)
                hr[kk] = __ldcg(hrow + kk * 32);
        }

        // partial gate sums over this warp's 32-k slice, all 4 units
        unsigned long long acc[4][2];
#pragma unroll
        for (int u = 0; u < 4; ++u) { acc[u][0] = 0ULL; acc[u][1] = 0ULL; }
        {
            const ulonglong2* up = &U4s[(w * 32) * 4];
#pragma unroll
            for (int kk = 0; kk < 32; ++kk) {
                unsigned long long h2 = pack2(hr[kk]);
                ulonglong2 u0 = up[kk * 4 + 0];
                ulonglong2 u1 = up[kk * 4 + 1];
                ulonglong2 u2 = up[kk * 4 + 2];
                ulonglong2 u3 = up[kk * 4 + 3];
                fma2(acc[0][0], h2, u0.x); fma2(acc[0][1], h2, u0.y);
                fma2(acc[1][0], h2, u1.x); fma2(acc[1][1], h2, u1.y);
                fma2(acc[2][0], h2, u2.x); fma2(acc[2][1], h2, u2.y);
                fma2(acc[3][0], h2, u3.x); fma2(acc[3][1], h2, u3.y);
            }
        }
        ulonglong2* rbuf = red2[s & 1];
#pragma unroll
        for (int u = 0; u < 4; ++u) {
            ulonglong2 pv; pv.x = acc[u][0]; pv.y = acc[u][1];
            rbuf[(w * 4 + u) * 32 + b] = pv;
        }
        __syncthreads();

        if (tid < 128) {
            unsigned long long aif = pack2b(xzv.x, xzv.y);
            unsigned long long ago = pack2b(xzv.z, xzv.w);
#pragma unroll
            for (int w2 = 0; w2 < 8; ++w2) {
                ulonglong2 pv = rbuf[(w2 * 4 + ur) * 32 + br];
                add2(aif, pv.x);
                add2(ago, pv.y);
            }
            float2 fif = unpack2(aif), fgo = unpack2(ago);
            float zi = fif.x, zf = fif.y, zg = fgo.x, zo = fgo.y;

            c = sig_p(zf) * c + sig_p(zi) * tanh_p(zg);
            float h = sig_p(zo) * tanh_p(c);

            const int u = uq * 4 + ur;
            g_hbuf[(s + 1) & 1][dir][u * 32 + br] = h;
            asm volatile("bar.sync 1, 128;" ::: "memory");
            if (tid == 0) {
                asm volatile("red.release.gpu.global.add.u32 [%0], %1;"
                             :: "l"(relp), "r"(1u) : "memory");
            }

            if (is_last)
                dout[((size_t)br * TT + t) * 512 + dir * 256 + u] = h;
            else
                xout[((size_t)t * NB + br) * 512 + dir * 256 + u] = h;

            if (s == TT - 1) {
                g_stateH[dir][u * 32 + br] = h;
                g_stateC[dir][u * 32 + br] = c;
                if (is_last && wstates) {
                    float* tail = dout + OUT_MAIN + (size_t)dir * 2 * NB * UU;
                    tail[br * UU + u] = h;
                    tail[NB * UU + br * UU + u] = c;
                }
            }
        }
    }
}

// ---------------- projection GEMM: C[65536,2048] = A[65536,512] @ W[512,2048] + bias ----
#define GBM 128
#define GBN 128
#define GBK 16
#define AS_LD 264
#define AS_BUF (GBK * AS_LD)
#define WS_BUF (GBK * GBN)
#define GEMM_SMEM ((2 * AS_BUF + 2 * WS_BUF) * 4)

__global__ void __launch_bounds__(256, 2)
gemm_kernel(int l) {
    extern __shared__ __align__(16) float gsm[];
    float* As = gsm;
    float* Ws = gsm + 2 * AS_BUF;

    const float* A = (l == 0) ? g_X1 : g_X2;
    const float* W = g_Wcat[l];
    const float* bias = g_bcat[l];
    float* C = g_xz;

    const int n0 = blockIdx.x * GBN;
    const int r0 = blockIdx.y * GBM;
    const int tid = threadIdx.x;
    const int tx = tid & 15;
    const int ty = tid >> 4;

    const int arow = tid >> 2;
    const int akq = tid & 3;
    const int wk = tid >> 5;
    const int wn = tid & 31;

    unsigned long long acc[8][4];
#pragma unroll
    for (int i = 0; i < 8; ++i)
#pragma unroll
        for (int j = 0; j < 4; ++j) acc[i][j] = 0ULL;

    const float* Ag = A + (size_t)(r0 + arow) * 512 + akq * 4;
    const float* Wg = W + (size_t)wk * 2048 + n0 + wn * 4;

    float4 ra0[2], ra1[2], rw0[2], rw1[2];
#pragma unroll
    for (int p = 0; p < 2; ++p) {
        ra0[p] = __ldg((const float4*)(Ag + p * 16));
        ra1[p] = __ldg((const float4*)(Ag + (size_t)64 * 512 + p * 16));
        rw0[p] = __ldg((const float4*)(Wg + (size_t)p * 16 * 2048));
        rw1[p] = __ldg((const float4*)(Wg + (size_t)p * 16 * 2048 + (size_t)8 * 2048));
    }

    for (int kt = 0; kt < 32; ++kt) {
        const int pp = kt & 1;
        float* as = As + pp * AS_BUF;
        float* ws = Ws + pp * WS_BUF;

        {
            float* d0 = as + (akq * 4 + 0) * AS_LD;
            float* d1 = as + (akq * 4 + 1) * AS_LD;
            float* d2 = as + (akq * 4 + 2) * AS_LD;
            float* d3 = as + (akq * 4 + 3) * AS_LD;
            int m0 = 2 * arow, m1 = 2 * (arow + 64);
            float4 a0 = ra0[pp], a1 = ra1[pp];
            d0[m0] = a0.x; d0[m0 + 1] = a0.x; d0[m1] = a1.x; d0[m1 + 1] = a1.x;
            d1[m0] = a0.y; d1[m0 + 1] = a0.y; d1[m1] = a1.y; d1[m1 + 1] = a1.y;
            d2[m0] = a0.z; d2[m0 + 1] = a0.z; d2[m1] = a1.z; d2[m1 + 1] = a1.z;
            d3[m0] = a0.w; d3[m0 + 1] = a0.w; d3[m1] = a1.w; d3[m1 + 1] = a1.w;
        }
        *(float4*)&ws[wk * GBN + wn * 4] = rw0[pp];
        *(float4*)&ws[(wk + 8) * GBN + wn * 4] = rw1[pp];
        __syncthreads();

        if (kt < 30) {
            ra0[pp] = __ldg((const float4*)(Ag + (kt + 2) * 16));
            ra1[pp] = __ldg((const float4*)(Ag + (size_t)64 * 512 + (kt + 2) * 16));
            rw0[pp] = __ldg((const float4*)(Wg + (size_t)(kt + 2) * 16 * 2048));
            rw1[pp] = __ldg((const float4*)(Wg + (size_t)(kt + 2) * 16 * 2048 + (size_t)8 * 2048));
        }

#pragma unroll
        for (int k = 0; k < GBK; ++k) {
            const float* ar = as + k * AS_LD + ty * 16;
            ulonglong2 a01 = *(const ulonglong2*)(ar);
            ulonglong2 a23 = *(const ulonglong2*)(ar + 4);
            ulonglong2 a45 = *(const ulonglong2*)(ar + 8);
            ulonglong2 a67 = *(const ulonglong2*)(ar + 12);
            const unsigned long long* wr =
                (const unsigned long long*)(ws + k * GBN + tx * 8);
            ulonglong2 w01 = *(const ulonglong2*)(wr);
            ulonglong2 w23 = *(const ulonglong2*)(wr + 2);

            unsigned long long am[8] = {a01.x, a01.y, a23.x, a23.y,
                                        a45.x, a45.y, a67.x, a67.y};
            unsigned long long wp[4] = {w01.x, w01.y, w23.x, w23.y};
#pragma unroll
            for (int m = 0; m < 8; ++m)
#pragma unroll
                for (int j = 0; j < 4; ++j) fma2(acc[m][j], am[m], wp[j]);
        }
        __syncthreads();
    }

    float4 bv0 = *(const float4*)&bias[n0 + tx * 8];
    float4 bv1 = *(const float4*)&bias[n0 + tx * 8 + 4];
#pragma unroll
    for (int m = 0; m < 8; ++m) {
        int row = r0 + ty * 8 + m;
        float2 p0 = unpack2(acc[m][0]);
        float2 p1 = unpack2(acc[m][1]);
        float2 p2 = unpack2(acc[m][2]);
        float2 p3 = unpack2(acc[m][3]);
        float4 o0 = make_float4(p0.x + bv0.x, p0.y + bv0.y, p1.x + bv0.z, p1.y + bv0.w);
        float4 o1 = make_float4(p2.x + bv1.x, p2.y + bv1.y, p3.x + bv1.z, p3.y + bv1.w);
        float* cp = &C[(size_t)row * 2048 + n0 + tx * 8];
        *(float4*)cp = o0;
        *(float4*)(cp + 4) = o1;
    }
}

// ---------------- launch ----------------
extern "C" void kernel_launch(void* const* d_in, const int* in_sizes, int n_in,
                              void* d_out, int out_size) {
    const float* inputs = (const float*)d_in[0];
    const float* W0f = (const float*)d_in[1];
    const float* U0f = (const float*)d_in[2];
    const float* b0f = (const float*)d_in[3];
    const float* W0b = (const float*)d_in[4];
    const float* U0b = (const float*)d_in[5];
    const float* b0b = (const float*)d_in[6];
    const float* Wf = (const float*)d_in[7];
    const float* Uf = (const float*)d_in[8];
    const float* bf = (const float*)d_in[9];
    const float* Wb = (const float*)d_in[10];
    const float* Ub = (const float*)d_in[11];
    const float* bb = (const float*)d_in[12];
    float* out = (float*)d_out;

    int wstates = ((size_t)out_size >= OUT_FULL) ? 1 : 0;

    cudaFuncSetAttribute(gemm_kernel, cudaFuncAttributeMaxDynamicSharedMemorySize,
                         GEMM_SMEM);
    cudaFuncSetAttribute(gemm_kernel, cudaFuncAttributePreferredSharedMemoryCarveout,
                         100);

    prep_kernel<<<512, 256>>>(W0f, U0f, b0f, W0b, U0b, b0b, Wf, Uf, bf, Wb, Ub, bb);

    // layer 0
    pre_recur_kernel<<<64, 256>>>(1);
    recur_kernel<<<128, 256>>>(inputs, out, 0, 0, 0);

    // layer 1
    gemm_kernel<<<dim3(16, 512), 256, GEMM_SMEM>>>(0);
    pre_recur_kernel<<<64, 256>>>(0);
    recur_kernel<<<128, 256>>>(nullptr, out, 1, 0, 0);

    // layer 2
    gemm_kernel<<<dim3(16, 512), 256, GEMM_SMEM>>>(1);
    pre_recur_kernel<<<64, 256>>>(0);
    recur_kernel<<<128, 256>>>(nullptr, out, 2, 1, wstates);
}

// round 16
// speedup vs baseline: 3.5424x; 1.0077x over previous
#include <cuda_runtime.h>
#include <cuda_bf16.h>
#include <cstdint>
#include <cstddef>

// Problem dims
#define TT 2048
#define NB 32
#define UU 256
#define OUT_MAIN ((size_t)NB * TT * 512)
#define OUT_FULL (OUT_MAIN + 4 * (size_t)NB * UU)

// ---------------- static device scratch ----------------
__device__ float g_xz[(size_t)TT * NB * 2048];   // [t*32+b][2048] gate preacts
__device__ float g_X1[(size_t)TT * NB * 512];    // layer0 output [t][b][512]
__device__ float g_X2[(size_t)TT * NB * 512];    // layer1 output
__device__ float g_Ure[3][2][UU * 1024];         // [layer][dir][k][u*4+g]
__device__ float g_Wcat[2][512 * 2048];          // [l][k][d*1024 + u*4+g]
__device__ float g_bcat[2][2048];
__device__ float g_W0re[2][1024];
__device__ float g_b0re[2][1024];
__device__ float g_hbuf[2][2][UU * NB];          // [phase][dir][k*32+b]
__device__ float g_stateH[2][UU * NB];
__device__ float g_stateC[2][UU * NB];
__device__ unsigned g_cntg[2 * 8 * 32];          // [dir][group] padded 128B

// ---------------- packed f32x2 helpers ----------------
__device__ __forceinline__ void fma2(unsigned long long& d, unsigned long long a,
                                     unsigned long long b) {
    asm("fma.rn.f32x2 %0, %1, %2, %0;" : "+l"(d) : "l"(a), "l"(b));
}
__device__ __forceinline__ void add2(unsigned long long& d, unsigned long long a) {
    asm("add.rn.f32x2 %0, %0, %1;" : "+l"(d) : "l"(a));
}
__device__ __forceinline__ unsigned long long pack2(float x) {
    unsigned long long r;
    asm("mov.b64 %0, {%1, %1};" : "=l"(r) : "f"(x));
    return r;
}
__device__ __forceinline__ unsigned long long pack2b(float x, float y) {
    unsigned long long r;
    asm("mov.b64 %0, {%1, %2};" : "=l"(r) : "f"(x), "f"(y));
    return r;
}
__device__ __forceinline__ float2 unpack2(unsigned long long v) {
    float2 f;
    asm("mov.b64 {%0, %1}, %2;" : "=f"(f.x), "=f"(f.y) : "l"(v));
    return f;
}

// ---------------- fast-math-immune activations ----------------
__device__ __forceinline__ float exp_p(float x) {
    float t = fminf(fmaxf(x, -87.0f), 87.0f);
    float n = rintf(t * 1.4426950408889634f);
    float f = fmaf(n, -0.693145751953125f, t);
    f = fmaf(n, -1.4286067653e-06f, f);
    float p = 1.9841270e-04f;
    p = fmaf(p, f, 1.3888889e-03f);
    p = fmaf(p, f, 8.3333333e-03f);
    p = fmaf(p, f, 4.1666668e-02f);
    p = fmaf(p, f, 1.6666667e-01f);
    p = fmaf(p, f, 0.5f);
    p = fmaf(p, f, 1.0f);
    p = fmaf(p, f, 1.0f);
    int ni = (int)n;
    float sc = __int_as_float((ni + 127) << 23);
    return p * sc;
}
__device__ __forceinline__ float rcp_nr(float d) {
    float r;
    asm("rcp.approx.f32 %0, %1;" : "=f"(r) : "f"(d));
    r = fmaf(r, fmaf(-d, r, 1.0f), r);
    return r;
}
__device__ __forceinline__ float sig_p(float x) {
    return rcp_nr(1.0f + exp_p(-x));
}
__device__ __forceinline__ float tanh_p(float x) {
    float a = fabsf(x);
    float e = exp_p(-2.0f * a);
    float r = (1.0f - e) * rcp_nr(1.0f + e);
    return copysignf(r, x);
}

// ---------------- weight rearrangement ----------------
__global__ void prep_kernel(const float* __restrict__ W0f, const float* __restrict__ U0f,
                            const float* __restrict__ b0f, const float* __restrict__ W0b,
                            const float* __restrict__ U0b, const float* __restrict__ b0b,
                            const float* __restrict__ Wf, const float* __restrict__ Uf,
                            const float* __restrict__ bf, const float* __restrict__ Wb,
                            const float* __restrict__ Ub, const float* __restrict__ bb) {
    int idx0 = blockIdx.x * blockDim.x + threadIdx.x;
    int stride = gridDim.x * blockDim.x;
    for (int i = idx0; i < 3 * 2 * 256 * 1024; i += stride) {
        int j = i & 1023;
        int k = (i >> 10) & 255;
        int d = (i >> 18) & 1;
        int l = i >> 19;
        int u = j >> 2, g = j & 3;
        const float* Us = (l == 0) ? (d ? U0b : U0f)
                                   : (d ? Ub + (size_t)(l - 1) * 256 * 1024
                                        : Uf + (size_t)(l - 1) * 256 * 1024);
        g_Ure[l][d][k * 1024 + j] = Us[k * 1024 + g * 256 + u];
    }
    for (int i = idx0; i < 2 * 512 * 2048; i += stride) {
        int j2 = i & 2047;
        int k = (i >> 11) & 511;
        int l = i >> 20;
        int d = j2 >> 10;
        int j = j2 & 1023;
        int u = j >> 2, g = j & 3;
        const float* Ws = d ? Wb : Wf;
        g_Wcat[l][k * 2048 + j2] = Ws[(size_t)l * 512 * 1024 + k * 1024 + g * 256 + u];
    }
    for (int i = idx0; i < 2 * 2048; i += stride) {
        int j2 = i & 2047;
        int l = i >> 11;
        int d = j2 >> 10;
        int j = j2 & 1023;
        int u = j >> 2, g = j & 3;
        const float* bs = d ? bb : bf;
        g_bcat[l][j2] = bs[l * 1024 + g * 256 + u];
    }
    for (int i = idx0; i < 2 * 1024; i += stride) {
        int j = i & 1023;
        int d = i >> 10;
        int u = j >> 2, g = j & 3;
        g_W0re[d][j] = (d ? W0b : W0f)[g * 256 + u];
        g_b0re[d][j] = (d ? b0b : b0f)[g * 256 + u];
    }
}

// ---------------- per-layer init ----------------
__global__ void pre_recur_kernel(int zero_init) {
    int idx = blockIdx.x * blockDim.x + threadIdx.x;
    int stride = gridDim.x * blockDim.x;
    for (int i = idx; i < 2 * 8 * 32; i += stride) g_cntg[i] = 0;
    float* hb = &g_hbuf[0][0][0];
    const float* sh = &g_stateH[0][0];
    float* sc = &g_stateC[0][0];
    for (int i = idx; i < 2 * UU * NB; i += stride) {
        hb[i] = zero_init ? 0.0f : sh[i];
        if (zero_init) sc[i] = 0.0f;
    }
}

// ---------------- recurrent kernel ----------------
// 128 CTAs (64/dir) x 256 threads. warp = 32-k chunk, lane = batch.
// Runner warps (4-7): partials -> bar.arrive -> run ahead into step s+1.
// Reducer warps (0-3): partials -> bar.sync -> reduce unit w -> act ->
// publish h -> per-warp red.release (target 32*s). Parity barrier ids +
// parity-double-buffered partials/hbuf; transitive poll closure bounds
// run-ahead to exactly 1 step.
__global__ void __launch_bounds__(256, 1)
recur_kernel(const float* __restrict__ x0, float* __restrict__ dout,
             int layer, int is_last, int wstates) {
    __shared__ __align__(16) ulonglong2 U4s[UU * 4];        // [k][unit] 16KB
    __shared__ __align__(16) ulonglong2 red2[2][32 * 32];   // [par][w*4+u][b] 32KB

    const int cta = blockIdx.x;
    const int dir = cta >> 6;
    const int uq = cta & 63;
    const int tid = threadIdx.x;
    const int w = tid >> 5;       // k-chunk / consumer group; w<4 also reducer for unit w
    const int b = tid & 31;       // batch lane

    // stage U slice: per k, 4 units x (if,go) float4
    {
        const float* Up = g_Ure[layer][dir];
        for (int i = tid; i < 1024; i += 256) {
            int k = i >> 2, u = i & 3;
            float4 v = *(const float4*)&Up[(size_t)k * 1024 + (uq * 4 + u) * 4];
            *(float4*)&U4s[k * 4 + u] = v;
        }
    }

    float4 w0v = make_float4(0.f, 0.f, 0.f, 0.f), b0v = w0v;
    float c = 0.0f;
    if (w < 4) {
        if (layer == 0) {
            w0v = *(const float4*)&g_W0re[dir][(uq * 4 + w) * 4];
            b0v = *(const float4*)&g_b0re[dir][(uq * 4 + w) * 4];
        }
        c = g_stateC[dir][(uq * 4 + w) * 32 + b];
    }

    float* xout = is_last ? dout : (layer == 0 ? g_X1 : g_X2);
    unsigned* pollp = &g_cntg[(dir * 8 + w) * 32];        // this warp's producer group
    unsigned* relp = &g_cntg[(dir * 8 + (uq >> 3)) * 32]; // this CTA's group
    const float* xzbase = g_xz + dir * 1024 + uq * 16 + w * 4;

    __syncthreads();

    for (int s = 0; s < TT; ++s) {
        const int t = dir ? (TT - 1 - s) : s;
        const int bid = 1 + (s & 1);   // parity barrier id

        // reducers prefetch input preacts (in flight during the poll)
        float4 xzv = make_float4(0.f, 0.f, 0.f, 0.f);
        if (w < 4) {
            if (layer == 0) {
                float xv = __ldg(&x0[(size_t)b * TT + t]);
                xzv.x = fmaf(xv, w0v.x, b0v.x);
                xzv.y = fmaf(xv, w0v.y, b0v.y);
                xzv.z = fmaf(xv, w0v.z, b0v.z);
                xzv.w = fmaf(xv, w0v.w, b0v.w);
            } else {
                xzv = __ldg((const float4*)(xzbase + ((size_t)t * NB + b) * 2048));
            }
        }

        // per-warp poll: 32 reducer-warp releases per group per step
        if (s > 0) {
            const unsigned target = 32u * (unsigned)s;
            unsigned v;
            do {
                asm volatile("ld.acquire.gpu.global.u32 %0, [%1];"
                             : "=r"(v) : "l"(pollp) : "memory");
            } while (v < target);
        }

        // load this warp's 32 h values straight into registers (coalesced)
        float hr[32];
        {
            const float* hrow = &g_hbuf[s & 1][dir][(w * 32) * 32 + b];
#pragma unroll
            for (int kk = 0; kk < 32; ++kk)
                hr[kk] = __ldcg(hrow + kk * 32);
        }

        // partial gate sums over this warp's 32-k slice, all 4 units
        unsigned long long acc[4][2];
#pragma unroll
        for (int u = 0; u < 4; ++u) { acc[u][0] = 0ULL; acc[u][1] = 0ULL; }
        {
            const ulonglong2* up = &U4s[(w * 32) * 4];
#pragma unroll
            for (int kk = 0; kk < 32; ++kk) {
                unsigned long long h2 = pack2(hr[kk]);
                ulonglong2 u0 = up[kk * 4 + 0];
                ulonglong2 u1 = up[kk * 4 + 1];
                ulonglong2 u2 = up[kk * 4 + 2];
                ulonglong2 u3 = up[kk * 4 + 3];
                fma2(acc[0][0], h2, u0.x); fma2(acc[0][1], h2, u0.y);
                fma2(acc[1][0], h2, u1.x); fma2(acc[1][1], h2, u1.y);
                fma2(acc[2][0], h2, u2.x); fma2(acc[2][1], h2, u2.y);
                fma2(acc[3][0], h2, u3.x); fma2(acc[3][1], h2, u3.y);
            }
        }
        ulonglong2* rbuf = red2[s & 1];
#pragma unroll
        for (int u = 0; u < 4; ++u) {
            ulonglong2 pv; pv.x = acc[u][0]; pv.y = acc[u][1];
            rbuf[(w * 4 + u) * 32 + b] = pv;
        }

        if (w >= 4) {
            // runner: signal partials ready, run ahead into step s+1
            asm volatile("bar.arrive %0, 256;" :: "r"(bid) : "memory");
            continue;
        }
        asm volatile("bar.sync %0, 256;" :: "r"(bid) : "memory");

        // reduce for unit u = uq*4 + w, batch b
        {
            unsigned long long aif = pack2b(xzv.x, xzv.y);
            unsigned long long ago = pack2b(xzv.z, xzv.w);
#pragma unroll
            for (int w2 = 0; w2 < 8; ++w2) {
                ulonglong2 pv = rbuf[(w2 * 4 + w) * 32 + b];
                add2(aif, pv.x);
                add2(ago, pv.y);
            }
            float2 fif = unpack2(aif), fgo = unpack2(ago);
            float zi = fif.x, zf = fif.y, zg = fgo.x, zo = fgo.y;

            c = sig_p(zf) * c + sig_p(zi) * tanh_p(zg);
            float h = sig_p(zo) * tanh_p(c);

            const int u = uq * 4 + w;
            g_hbuf[(s + 1) & 1][dir][u * 32 + b] = h;
            __syncwarp();
            if (b == 0) {
                asm volatile("red.release.gpu.global.add.u32 [%0], %1;"
                             :: "l"(relp), "r"(1u) : "memory");
            }

            if (is_last)
                dout[((size_t)b * TT + t) * 512 + dir * 256 + u] = h;
            else
                xout[((size_t)t * NB + b) * 512 + dir * 256 + u] = h;

            if (s == TT - 1) {
                g_stateH[dir][u * 32 + b] = h;
                g_stateC[dir][u * 32 + b] = c;
                if (is_last && wstates) {
                    float* tail = dout + OUT_MAIN + (size_t)dir * 2 * NB * UU;
                    tail[b * UU + u] = h;
                    tail[NB * UU + b * UU + u] = c;
                }
            }
        }
    }
}

// ---------------- projection GEMM: C[65536,2048] = A[65536,512] @ W[512,2048] + bias ----
// A stored [k][m] (no dup): a-frags via broadcast LDS.128, packed in registers.
#define GBM 128
#define GBN 128
#define GBK 16
#define AS_LD2 132
#define AS_BUF2 (GBK * AS_LD2)
#define WS_BUF (GBK * GBN)
#define GEMM_SMEM ((2 * AS_BUF2 + 2 * WS_BUF) * 4)

__global__ void __launch_bounds__(256, 2)
gemm_kernel(int l) {
    extern __shared__ __align__(16) float gsm[];
    float* As = gsm;
    float* Ws = gsm + 2 * AS_BUF2;

    const float* A = (l == 0) ? g_X1 : g_X2;
    const float* W = g_Wcat[l];
    const float* bias = g_bcat[l];
    float* C = g_xz;

    const int n0 = blockIdx.x * GBN;
    const int r0 = blockIdx.y * GBM;
    const int tid = threadIdx.x;
    const int tx = tid & 15;
    const int ty = tid >> 4;

    const int arow = tid >> 2;
    const int akq = tid & 3;
    const int wk = tid >> 5;
    const int wn = tid & 31;

    unsigned long long acc[8][4];
#pragma unroll
    for (int i = 0; i < 8; ++i)
#pragma unroll
        for (int j = 0; j < 4; ++j) acc[i][j] = 0ULL;

    const float* Ag = A + (size_t)(r0 + arow) * 512 + akq * 4;
    const float* Wg = W + (size_t)wk * 2048 + n0 + wn * 4;

    float4 ra0[2], ra1[2], rw0[2], rw1[2];
#pragma unroll
    for (int p = 0; p < 2; ++p) {
        ra0[p] = __ldg((const float4*)(Ag + p * 16));
        ra1[p] = __ldg((const float4*)(Ag + (size_t)64 * 512 + p * 16));
        rw0[p] = __ldg((const float4*)(Wg + (size_t)p * 16 * 2048));
        rw1[p] = __ldg((const float4*)(Wg + (size_t)p * 16 * 2048 + (size_t)8 * 2048));
    }

    for (int kt = 0; kt < 32; ++kt) {
        const int pp = kt & 1;
        float* as = As + pp * AS_BUF2;
        float* ws = Ws + pp * WS_BUF;

        {
            float* d0 = as + (akq * 4 + 0) * AS_LD2;
            float* d1 = as + (akq * 4 + 1) * AS_LD2;
            float* d2 = as + (akq * 4 + 2) * AS_LD2;
            float* d3 = as + (akq * 4 + 3) * AS_LD2;
            float4 a0 = ra0[pp], a1 = ra1[pp];
            d0[arow] = a0.x; d0[arow + 64] = a1.x;
            d1[arow] = a0.y; d1[arow + 64] = a1.y;
            d2[arow] = a0.z; d2[arow + 64] = a1.z;
            d3[arow] = a0.w; d3[arow + 64] = a1.w;
        }
        *(float4*)&ws[wk * GBN + wn * 4] = rw0[pp];
        *(float4*)&ws[(wk + 8) * GBN + wn * 4] = rw1[pp];
        __syncthreads();

        if (kt < 30) {
            ra0[pp] = __ldg((const float4*)(Ag + (kt + 2) * 16));
            ra1[pp] = __ldg((const float4*)(Ag + (size_t)64 * 512 + (kt + 2) * 16));
            rw0[pp] = __ldg((const float4*)(Wg + (size_t)(kt + 2) * 16 * 2048));
            rw1[pp] = __ldg((const float4*)(Wg + (size_t)(kt + 2) * 16 * 2048 + (size_t)8 * 2048));
        }

#pragma unroll
        for (int k = 0; k < GBK; ++k) {
            const float* ar = as + k * AS_LD2 + ty * 8;
            float4 af0 = *(const float4*)ar;
            float4 af1 = *(const float4*)(ar + 4);
            const unsigned long long* wr =
                (const unsigned long long*)(ws + k * GBN + tx * 8);
            ulonglong2 w01 = *(const ulonglong2*)(wr);
            ulonglong2 w23 = *(const ulonglong2*)(wr + 2);

            unsigned long long am[8] = {pack2(af0.x), pack2(af0.y),
                                        pack2(af0.z), pack2(af0.w),
                                        pack2(af1.x), pack2(af1.y),
                                        pack2(af1.z), pack2(af1.w)};
            unsigned long long wp[4] = {w01.x, w01.y, w23.x, w23.y};
#pragma unroll
            for (int m = 0; m < 8; ++m)
#pragma unroll
                for (int j = 0; j < 4; ++j) fma2(acc[m][j], am[m], wp[j]);
        }
        __syncthreads();
    }

    float4 bv0 = *(const float4*)&bias[n0 + tx * 8];
    float4 bv1 = *(const float4*)&bias[n0 + tx * 8 + 4];
#pragma unroll
    for (int m = 0; m < 8; ++m) {
        int row = r0 + ty * 8 + m;
        float2 p0 = unpack2(acc[m][0]);
        float2 p1 = unpack2(acc[m][1]);
        float2 p2 = unpack2(acc[m][2]);
        float2 p3 = unpack2(acc[m][3]);
        float4 o0 = make_float4(p0.x + bv0.x, p0.y + bv0.y, p1.x + bv0.z, p1.y + bv0.w);
        float4 o1 = make_float4(p2.x + bv1.x, p2.y + bv1.y, p3.x + bv1.z, p3.y + bv1.w);
        float* cp = &C[(size_t)row * 2048 + n0 + tx * 8];
        *(float4*)cp = o0;
        *(float4*)(cp + 4) = o1;
    }
}

// ---------------- launch ----------------
extern "C" void kernel_launch(void* const* d_in, const int* in_sizes, int n_in,
                              void* d_out, int out_size) {
    const float* inputs = (const float*)d_in[0];
    const float* W0f = (const float*)d_in[1];
    const float* U0f = (const float*)d_in[2];
    const float* b0f = (const float*)d_in[3];
    const float* W0b = (const float*)d_in[4];
    const float* U0b = (const float*)d_in[5];
    const float* b0b = (const float*)d_in[6];
    const float* Wf = (const float*)d_in[7];
    const float* Uf = (const float*)d_in[8];
    const float* bf = (const float*)d_in[9];
    const float* Wb = (const float*)d_in[10];
    const float* Ub = (const float*)d_in[11];
    const float* bb = (const float*)d_in[12];
    float* out = (float*)d_out;

    int wstates = ((size_t)out_size >= OUT_FULL) ? 1 : 0;

    cudaFuncSetAttribute(gemm_kernel, cudaFuncAttributeMaxDynamicSharedMemorySize,
                         GEMM_SMEM);
    cudaFuncSetAttribute(gemm_kernel, cudaFuncAttributePreferredSharedMemoryCarveout,
                         100);

    prep_kernel<<<512, 256>>>(W0f, U0f, b0f, W0b, U0b, b0b, Wf, Uf, bf, Wb, Ub, bb);

    // layer 0
    pre_recur_kernel<<<64, 256>>>(1);
    recur_kernel<<<128, 256>>>(inputs, out, 0, 0, 0);

    // layer 1
    gemm_kernel<<<dim3(16, 512), 256, GEMM_SMEM>>>(0);
    pre_recur_kernel<<<64, 256>>>(0);
    recur_kernel<<<128, 256>>>(nullptr, out, 1, 0, 0);

    // layer 2
    gemm_kernel<<<dim3(16, 512), 256, GEMM_SMEM>>>(1);
    pre_recur_kernel<<<64, 256>>>(0);
    recur_kernel<<<128, 256>>>(nullptr, out, 2, 1, wstates);
}